// round 1
// baseline (speedup 1.0000x reference)
#include <cuda_runtime.h>
#include <math.h>
#include <stdint.h>

// Problem constants
// B=8, T=2048, D=1024 ; M1 = B*T = 16384
#define NTHREADS 256

// ---------------------------------------------------------------------------
// Scratch (static device allocations -- allowed; cudaMalloc is not)
// ---------------------------------------------------------------------------
__device__ float g_proj[(size_t)16384 * 3072];  // q|k|v        192 MB
__device__ float g_kv  [(size_t)16384 * 2048];  // ke*v | ke    128 MB
__device__ float g_eb  [(size_t)2048  * 2048];  // expbias       16 MB
__device__ float g_s   [(size_t)16384 * 2048];  // num | denom  128 MB
__device__ float g_y   [(size_t)16384 * 1024];  // pre-proj      64 MB

// ---------------------------------------------------------------------------
// Generic fp32 GEMM: C[M,N] = A[M,K] @ B[K,N], row-major, optional batch (z)
// 128x128 tile, BK=16, 256 threads, 8x8 per thread (4+4 split), reg prefetch.
// Requires M%128==0, N%128==0, K%16==0 (true for all three call sites).
// ---------------------------------------------------------------------------
__global__ __launch_bounds__(256, 2)
void gemm_f32(const float* __restrict__ A, const float* __restrict__ B,
              float* __restrict__ C, int M, int N, int K,
              long sA, long sB, long sC)
{
    A += (long)blockIdx.z * sA;
    B += (long)blockIdx.z * sB;
    C += (long)blockIdx.z * sC;

    __shared__ __align__(16) float As[16][132];  // transposed, padded (132*4B %16==0)
    __shared__ __align__(16) float Bs[16][128];

    const int tid = threadIdx.x;
    const int bm  = blockIdx.y * 128;
    const int bn  = blockIdx.x * 128;

    const int tx = tid & 15;         // N direction
    const int ty = tid >> 4;         // M direction
    const int m0 = ty * 4;           // rows m0..m0+3 and m0+64..m0+67
    const int n0 = tx * 4;

    // A-tile loader mapping: 128 rows x 4 float4; 2 loads/thread
    const int aRow0 = tid >> 2;          // 0..63
    const int aC    = (tid & 3) * 4;     // 0,4,8,12
    // B-tile loader mapping: 16 rows x 32 float4; 2 loads/thread
    const int bRow0 = tid >> 5;          // 0..7
    const int bC    = (tid & 31) * 4;    // 0..124

    const float* Ap0 = A + (size_t)(bm + aRow0)      * K + aC;
    const float* Ap1 = A + (size_t)(bm + aRow0 + 64) * K + aC;
    const float* Bp0 = B + (size_t)bRow0       * N + bn + bC;
    const float* Bp1 = B + (size_t)(bRow0 + 8) * N + bn + bC;

    float acc[8][8];
    #pragma unroll
    for (int i = 0; i < 8; ++i)
        #pragma unroll
        for (int j = 0; j < 8; ++j) acc[i][j] = 0.0f;

    // prefetch tile 0 into registers
    float4 a0 = *(const float4*)Ap0;
    float4 a1 = *(const float4*)Ap1;
    float4 b0 = *(const float4*)Bp0;
    float4 b1 = *(const float4*)Bp1;

    const int KT = K >> 4;
    for (int kt = 0; kt < KT; ++kt) {
        // commit prefetched tile to smem
        As[aC + 0][aRow0] = a0.x;  As[aC + 1][aRow0] = a0.y;
        As[aC + 2][aRow0] = a0.z;  As[aC + 3][aRow0] = a0.w;
        As[aC + 0][aRow0 + 64] = a1.x;  As[aC + 1][aRow0 + 64] = a1.y;
        As[aC + 2][aRow0 + 64] = a1.z;  As[aC + 3][aRow0 + 64] = a1.w;
        *(float4*)&Bs[bRow0][bC]     = b0;
        *(float4*)&Bs[bRow0 + 8][bC] = b1;
        __syncthreads();

        // prefetch next tile (overlaps with compute below)
        if (kt + 1 < KT) {
            const int ko = (kt + 1) * 16;
            a0 = *(const float4*)(Ap0 + ko);
            a1 = *(const float4*)(Ap1 + ko);
            b0 = *(const float4*)(Bp0 + (size_t)ko * N);
            b1 = *(const float4*)(Bp1 + (size_t)ko * N);
        }

        #pragma unroll
        for (int k = 0; k < 16; ++k) {
            float4 A0 = *(const float4*)&As[k][m0];
            float4 A1 = *(const float4*)&As[k][m0 + 64];
            float4 B0 = *(const float4*)&Bs[k][n0];
            float4 B1 = *(const float4*)&Bs[k][n0 + 64];
            float av[8] = {A0.x, A0.y, A0.z, A0.w, A1.x, A1.y, A1.z, A1.w};
            float bv[8] = {B0.x, B0.y, B0.z, B0.w, B1.x, B1.y, B1.z, B1.w};
            #pragma unroll
            for (int i = 0; i < 8; ++i)
                #pragma unroll
                for (int j = 0; j < 8; ++j)
                    acc[i][j] = fmaf(av[i], bv[j], acc[i][j]);
        }
        __syncthreads();
    }

    // epilogue
    #pragma unroll
    for (int i = 0; i < 8; ++i) {
        const int r = bm + ((i < 4) ? (m0 + i) : (m0 + 60 + i));  // m0+64+(i-4)
        float4 o0 = make_float4(acc[i][0], acc[i][1], acc[i][2], acc[i][3]);
        float4 o1 = make_float4(acc[i][4], acc[i][5], acc[i][6], acc[i][7]);
        *(float4*)&C[(size_t)r * N + bn + n0]      = o0;
        *(float4*)&C[(size_t)r * N + bn + n0 + 64] = o1;
    }
}

// ---------------------------------------------------------------------------
// kv_kernel: per (b,t) row -> key_e = exp(k - rowmax(k)); out = [ke*v | ke]
// one block per row; 256 threads * float4 covers D=1024 in one pass
// ---------------------------------------------------------------------------
__global__ __launch_bounds__(256)
void kv_kernel(const float* __restrict__ proj, float* __restrict__ kv)
{
    const int row = blockIdx.x;                       // b*T + t
    const float* kp = proj + (size_t)row * 3072 + 1024;
    const float* vp = kp + 1024;
    const int t = threadIdx.x;

    float4 kk = *(const float4*)&kp[t * 4];
    float m = fmaxf(fmaxf(kk.x, kk.y), fmaxf(kk.z, kk.w));

    __shared__ float sm[8];
    #pragma unroll
    for (int o = 16; o > 0; o >>= 1) m = fmaxf(m, __shfl_xor_sync(0xffffffffu, m, o));
    if ((t & 31) == 0) sm[t >> 5] = m;
    __syncthreads();
    float mm = sm[0];
    #pragma unroll
    for (int w = 1; w < 8; ++w) mm = fmaxf(mm, sm[w]);

    float4 vv = *(const float4*)&vp[t * 4];
    float4 ke;
    ke.x = expf(kk.x - mm); ke.y = expf(kk.y - mm);
    ke.z = expf(kk.z - mm); ke.w = expf(kk.w - mm);

    float* out = kv + (size_t)row * 2048;
    float4 nv = make_float4(ke.x * vv.x, ke.y * vv.y, ke.z * vv.z, ke.w * vv.w);
    *(float4*)&out[t * 4]        = nv;
    *(float4*)&out[1024 + t * 4] = ke;
}

// ---------------------------------------------------------------------------
// expbias_kernel: row i -> exp(pos_bias[i,j] - max_{j<=i}) for j<=i, else 0
// ---------------------------------------------------------------------------
__global__ __launch_bounds__(256)
void expbias_kernel(const float* __restrict__ pb, float* __restrict__ eb)
{
    const int i = blockIdx.x;
    const float* row = pb + (size_t)i * 2048;
    const int t = threadIdx.x;

    float m = -INFINITY;
    for (int j = t; j <= i; j += 256) m = fmaxf(m, row[j]);

    __shared__ float sm[8];
    #pragma unroll
    for (int o = 16; o > 0; o >>= 1) m = fmaxf(m, __shfl_xor_sync(0xffffffffu, m, o));
    if ((t & 31) == 0) sm[t >> 5] = m;
    __syncthreads();
    float mm = sm[0];
    #pragma unroll
    for (int w = 1; w < 8; ++w) mm = fmaxf(mm, sm[w]);

    float* o = eb + (size_t)i * 2048;
    for (int j = t; j < 2048; j += 256)
        o[j] = (j <= i) ? expf(row[j] - mm) : 0.0f;
}

// ---------------------------------------------------------------------------
// combine_kernel: y = sigmoid(q) * num / denom    (float4 over 16M elements)
// ---------------------------------------------------------------------------
__global__ __launch_bounds__(256)
void combine_kernel(const float* __restrict__ proj, const float* __restrict__ s,
                    float* __restrict__ y)
{
    const size_t i4  = (size_t)blockIdx.x * 256 + threadIdx.x; // 0..4194303
    const size_t row = i4 >> 8;       // /256  -> b*T+t
    const size_t d4  = (i4 & 255) * 4;

    float4 q   = *(const float4*)&proj[row * 3072 + d4];
    float4 num = *(const float4*)&s[row * 2048 + d4];
    float4 den = *(const float4*)&s[row * 2048 + 1024 + d4];

    float4 r;
    r.x = (num.x / den.x) / (1.0f + expf(-q.x));
    r.y = (num.y / den.y) / (1.0f + expf(-q.y));
    r.z = (num.z / den.z) / (1.0f + expf(-q.z));
    r.w = (num.w / den.w) / (1.0f + expf(-q.w));
    *(float4*)&y[i4 * 4] = r;
}

// ---------------------------------------------------------------------------
// Launch
// ---------------------------------------------------------------------------
extern "C" void kernel_launch(void* const* d_in, const int* in_sizes, int n_in,
                              void* d_out, int out_size)
{
    // Identify inputs robustly by element count (all distinct):
    //   x: 16777216, w_attn: 3145728, w_proj: 1048576, pos_bias: 4194304
    const float* x = nullptr; const float* w_attn = nullptr;
    const float* w_proj = nullptr; const float* pos_bias = nullptr;
    for (int i = 0; i < n_in; ++i) {
        switch (in_sizes[i]) {
            case 16777216: x        = (const float*)d_in[i]; break;
            case 3145728:  w_attn   = (const float*)d_in[i]; break;
            case 1048576:  w_proj   = (const float*)d_in[i]; break;
            case 4194304:  pos_bias = (const float*)d_in[i]; break;
            default: break;
        }
    }
    float* out = (float*)d_out;

    float *proj, *kv, *eb, *s, *y;
    cudaGetSymbolAddress((void**)&proj, g_proj);
    cudaGetSymbolAddress((void**)&kv,   g_kv);
    cudaGetSymbolAddress((void**)&eb,   g_eb);
    cudaGetSymbolAddress((void**)&s,    g_s);
    cudaGetSymbolAddress((void**)&y,    g_y);

    // 1) expbias (independent of x) -- launched first to overlap nothing but cheap
    expbias_kernel<<<2048, 256>>>(pos_bias, eb);

    // 2) proj = x @ w_attn : [16384,1024] @ [1024,3072]
    gemm_f32<<<dim3(3072 / 128, 16384 / 128, 1), 256>>>(
        x, w_attn, proj, 16384, 3072, 1024, 0, 0, 0);

    // 3) kv = [key_e * value | key_e]
    kv_kernel<<<16384, 256>>>(proj, kv);

    // 4) s[b] = expbias @ kv[b] : batched [2048,2048] @ [2048,2048], A shared
    gemm_f32<<<dim3(2048 / 128, 2048 / 128, 8), 256>>>(
        eb, kv, s, 2048, 2048, 2048,
        0, (long)2048 * 2048, (long)2048 * 2048);

    // 5) y = sigmoid(q) * num / denom
    combine_kernel<<<16384, 256>>>(proj, s, y);

    // 6) out = y @ w_proj : [16384,1024] @ [1024,1024]
    gemm_f32<<<dim3(1024 / 128, 16384 / 128, 1), 256>>>(
        y, w_proj, out, 16384, 1024, 1024, 0, 0, 0);
}

// round 2
// speedup vs baseline: 1.0024x; 1.0024x over previous
#include <cuda_runtime.h>
#include <math.h>
#include <stdint.h>

// Problem constants
// B=8, T=2048, D=1024 ; M1 = B*T = 16384
#define NTHREADS 256

// ---------------------------------------------------------------------------
// Scratch (static device allocations -- allowed; cudaMalloc is not)
// ---------------------------------------------------------------------------
__device__ float g_proj[(size_t)16384 * 3072];  // q|k|v        192 MB
__device__ float g_kv  [(size_t)16384 * 2048];  // ke*v | ke    128 MB
__device__ float g_eb  [(size_t)2048  * 2048];  // expbias       16 MB
__device__ float g_s   [(size_t)16384 * 2048];  // num | denom  128 MB
__device__ float g_y   [(size_t)16384 * 1024];  // pre-proj      64 MB

// ---------------------------------------------------------------------------
// Generic fp32 GEMM: C[M,N] = A[M,K] @ B[K,N], row-major, optional batch (z)
// 128x128 tile, BK=16, 256 threads, 8x8 per thread (4+4 split), reg prefetch.
// Requires M%128==0, N%128==0, K%16==0 (true for all three call sites).
// ---------------------------------------------------------------------------
__global__ __launch_bounds__(256, 2)
void gemm_f32(const float* __restrict__ A, const float* __restrict__ B,
              float* __restrict__ C, int M, int N, int K,
              long sA, long sB, long sC)
{
    A += (long)blockIdx.z * sA;
    B += (long)blockIdx.z * sB;
    C += (long)blockIdx.z * sC;

    __shared__ __align__(16) float As[16][132];  // transposed, padded (132*4B %16==0)
    __shared__ __align__(16) float Bs[16][128];

    const int tid = threadIdx.x;
    const int bm  = blockIdx.y * 128;
    const int bn  = blockIdx.x * 128;

    const int tx = tid & 15;         // N direction
    const int ty = tid >> 4;         // M direction
    const int m0 = ty * 4;           // rows m0..m0+3 and m0+64..m0+67
    const int n0 = tx * 4;

    // A-tile loader mapping: 128 rows x 4 float4; 2 loads/thread
    const int aRow0 = tid >> 2;          // 0..63
    const int aC    = (tid & 3) * 4;     // 0,4,8,12
    // B-tile loader mapping: 16 rows x 32 float4; 2 loads/thread
    const int bRow0 = tid >> 5;          // 0..7
    const int bC    = (tid & 31) * 4;    // 0..124

    const float* Ap0 = A + (size_t)(bm + aRow0)      * K + aC;
    const float* Ap1 = A + (size_t)(bm + aRow0 + 64) * K + aC;
    const float* Bp0 = B + (size_t)bRow0       * N + bn + bC;
    const float* Bp1 = B + (size_t)(bRow0 + 8) * N + bn + bC;

    float acc[8][8];
    #pragma unroll
    for (int i = 0; i < 8; ++i)
        #pragma unroll
        for (int j = 0; j < 8; ++j) acc[i][j] = 0.0f;

    // prefetch tile 0 into registers
    float4 a0 = *(const float4*)Ap0;
    float4 a1 = *(const float4*)Ap1;
    float4 b0 = *(const float4*)Bp0;
    float4 b1 = *(const float4*)Bp1;

    const int KT = K >> 4;
    for (int kt = 0; kt < KT; ++kt) {
        // commit prefetched tile to smem
        As[aC + 0][aRow0] = a0.x;  As[aC + 1][aRow0] = a0.y;
        As[aC + 2][aRow0] = a0.z;  As[aC + 3][aRow0] = a0.w;
        As[aC + 0][aRow0 + 64] = a1.x;  As[aC + 1][aRow0 + 64] = a1.y;
        As[aC + 2][aRow0 + 64] = a1.z;  As[aC + 3][aRow0 + 64] = a1.w;
        *(float4*)&Bs[bRow0][bC]     = b0;
        *(float4*)&Bs[bRow0 + 8][bC] = b1;
        __syncthreads();

        // prefetch next tile (overlaps with compute below)
        if (kt + 1 < KT) {
            const int ko = (kt + 1) * 16;
            a0 = *(const float4*)(Ap0 + ko);
            a1 = *(const float4*)(Ap1 + ko);
            b0 = *(const float4*)(Bp0 + (size_t)ko * N);
            b1 = *(const float4*)(Bp1 + (size_t)ko * N);
        }

        #pragma unroll
        for (int k = 0; k < 16; ++k) {
            float4 A0 = *(const float4*)&As[k][m0];
            float4 A1 = *(const float4*)&As[k][m0 + 64];
            float4 B0 = *(const float4*)&Bs[k][n0];
            float4 B1 = *(const float4*)&Bs[k][n0 + 64];
            float av[8] = {A0.x, A0.y, A0.z, A0.w, A1.x, A1.y, A1.z, A1.w};
            float bv[8] = {B0.x, B0.y, B0.z, B0.w, B1.x, B1.y, B1.z, B1.w};
            #pragma unroll
            for (int i = 0; i < 8; ++i)
                #pragma unroll
                for (int j = 0; j < 8; ++j)
                    acc[i][j] = fmaf(av[i], bv[j], acc[i][j]);
        }
        __syncthreads();
    }

    // epilogue
    #pragma unroll
    for (int i = 0; i < 8; ++i) {
        const int r = bm + ((i < 4) ? (m0 + i) : (m0 + 60 + i));  // m0+64+(i-4)
        float4 o0 = make_float4(acc[i][0], acc[i][1], acc[i][2], acc[i][3]);
        float4 o1 = make_float4(acc[i][4], acc[i][5], acc[i][6], acc[i][7]);
        *(float4*)&C[(size_t)r * N + bn + n0]      = o0;
        *(float4*)&C[(size_t)r * N + bn + n0 + 64] = o1;
    }
}

// ---------------------------------------------------------------------------
// kv_kernel: per (b,t) row -> key_e = exp(k - rowmax(k)); out = [ke*v | ke]
// one block per row; 256 threads * float4 covers D=1024 in one pass
// ---------------------------------------------------------------------------
__global__ __launch_bounds__(256)
void kv_kernel(const float* __restrict__ proj, float* __restrict__ kv)
{
    const int row = blockIdx.x;                       // b*T + t
    const float* kp = proj + (size_t)row * 3072 + 1024;
    const float* vp = kp + 1024;
    const int t = threadIdx.x;

    float4 kk = *(const float4*)&kp[t * 4];
    float m = fmaxf(fmaxf(kk.x, kk.y), fmaxf(kk.z, kk.w));

    __shared__ float sm[8];
    #pragma unroll
    for (int o = 16; o > 0; o >>= 1) m = fmaxf(m, __shfl_xor_sync(0xffffffffu, m, o));
    if ((t & 31) == 0) sm[t >> 5] = m;
    __syncthreads();
    float mm = sm[0];
    #pragma unroll
    for (int w = 1; w < 8; ++w) mm = fmaxf(mm, sm[w]);

    float4 vv = *(const float4*)&vp[t * 4];
    float4 ke;
    ke.x = expf(kk.x - mm); ke.y = expf(kk.y - mm);
    ke.z = expf(kk.z - mm); ke.w = expf(kk.w - mm);

    float* out = kv + (size_t)row * 2048;
    float4 nv = make_float4(ke.x * vv.x, ke.y * vv.y, ke.z * vv.z, ke.w * vv.w);
    *(float4*)&out[t * 4]        = nv;
    *(float4*)&out[1024 + t * 4] = ke;
}

// ---------------------------------------------------------------------------
// expbias_kernel: row i -> exp(pos_bias[i,j] - max_{j<=i}) for j<=i, else 0
// ---------------------------------------------------------------------------
__global__ __launch_bounds__(256)
void expbias_kernel(const float* __restrict__ pb, float* __restrict__ eb)
{
    const int i = blockIdx.x;
    const float* row = pb + (size_t)i * 2048;
    const int t = threadIdx.x;

    float m = -INFINITY;
    for (int j = t; j <= i; j += 256) m = fmaxf(m, row[j]);

    __shared__ float sm[8];
    #pragma unroll
    for (int o = 16; o > 0; o >>= 1) m = fmaxf(m, __shfl_xor_sync(0xffffffffu, m, o));
    if ((t & 31) == 0) sm[t >> 5] = m;
    __syncthreads();
    float mm = sm[0];
    #pragma unroll
    for (int w = 1; w < 8; ++w) mm = fmaxf(mm, sm[w]);

    float* o = eb + (size_t)i * 2048;
    for (int j = t; j < 2048; j += 256)
        o[j] = (j <= i) ? expf(row[j] - mm) : 0.0f;
}

// ---------------------------------------------------------------------------
// combine_kernel: y = sigmoid(q) * num / denom    (float4 over 16M elements)
// ---------------------------------------------------------------------------
__global__ __launch_bounds__(256)
void combine_kernel(const float* __restrict__ proj, const float* __restrict__ s,
                    float* __restrict__ y)
{
    const size_t i4  = (size_t)blockIdx.x * 256 + threadIdx.x; // 0..4194303
    const size_t row = i4 >> 8;       // /256  -> b*T+t
    const size_t d4  = (i4 & 255) * 4;

    float4 q   = *(const float4*)&proj[row * 3072 + d4];
    float4 num = *(const float4*)&s[row * 2048 + d4];
    float4 den = *(const float4*)&s[row * 2048 + 1024 + d4];

    float4 r;
    r.x = (num.x / den.x) / (1.0f + expf(-q.x));
    r.y = (num.y / den.y) / (1.0f + expf(-q.y));
    r.z = (num.z / den.z) / (1.0f + expf(-q.z));
    r.w = (num.w / den.w) / (1.0f + expf(-q.w));
    *(float4*)&y[i4 * 4] = r;
}

// ---------------------------------------------------------------------------
// Launch
// ---------------------------------------------------------------------------
extern "C" void kernel_launch(void* const* d_in, const int* in_sizes, int n_in,
                              void* d_out, int out_size)
{
    // Identify inputs robustly by element count (all distinct):
    //   x: 16777216, w_attn: 3145728, w_proj: 1048576, pos_bias: 4194304
    const float* x = nullptr; const float* w_attn = nullptr;
    const float* w_proj = nullptr; const float* pos_bias = nullptr;
    for (int i = 0; i < n_in; ++i) {
        switch (in_sizes[i]) {
            case 16777216: x        = (const float*)d_in[i]; break;
            case 3145728:  w_attn   = (const float*)d_in[i]; break;
            case 1048576:  w_proj   = (const float*)d_in[i]; break;
            case 4194304:  pos_bias = (const float*)d_in[i]; break;
            default: break;
        }
    }
    float* out = (float*)d_out;

    float *proj, *kv, *eb, *s, *y;
    cudaGetSymbolAddress((void**)&proj, g_proj);
    cudaGetSymbolAddress((void**)&kv,   g_kv);
    cudaGetSymbolAddress((void**)&eb,   g_eb);
    cudaGetSymbolAddress((void**)&s,    g_s);
    cudaGetSymbolAddress((void**)&y,    g_y);

    // 1) expbias (independent of x) -- launched first to overlap nothing but cheap
    expbias_kernel<<<2048, 256>>>(pos_bias, eb);

    // 2) proj = x @ w_attn : [16384,1024] @ [1024,3072]
    gemm_f32<<<dim3(3072 / 128, 16384 / 128, 1), 256>>>(
        x, w_attn, proj, 16384, 3072, 1024, 0, 0, 0);

    // 3) kv = [key_e * value | key_e]
    kv_kernel<<<16384, 256>>>(proj, kv);

    // 4) s[b] = expbias @ kv[b] : batched [2048,2048] @ [2048,2048], A shared
    gemm_f32<<<dim3(2048 / 128, 2048 / 128, 8), 256>>>(
        eb, kv, s, 2048, 2048, 2048,
        0, (long)2048 * 2048, (long)2048 * 2048);

    // 5) y = sigmoid(q) * num / denom
    combine_kernel<<<16384, 256>>>(proj, s, y);

    // 6) out = y @ w_proj : [16384,1024] @ [1024,1024]
    gemm_f32<<<dim3(1024 / 128, 16384 / 128, 1), 256>>>(
        y, w_proj, out, 16384, 1024, 1024, 0, 0, 0);
}